// round 4
// baseline (speedup 1.0000x reference)
#include <cuda_runtime.h>
#include <cuda_bf16.h>

// Problem constants
#define BB 4
#define SS 2048
#define CC 1024
#define EE 1024
#define HH 16
#define DD 64
#define BS (BB * SS)        // 8192
#define N_QKV (3 * EE)      // 3072

// Scratch (static device globals — no runtime allocation allowed)
__device__ float g_q[BB * HH * SS * DD];   // [B,H,S,D], pre-scaled by 1/sqrt(D)
__device__ float g_k[BB * HH * SS * DD];
__device__ float g_v[BB * HH * SS * DD];
__device__ float g_att[BS * EE];           // [B,S,E] attention output (pre out-proj)

// ---------------------------------------------------------------------------
// Classic pipelined SGEMM: C[M,N] = A[M,K] @ B[K,N], 128x128 tile, BK=8,
// 256 threads, 8x8 per-thread microtile.
// MODE 0: A=x, B=w_qkv; epilogue adds b_qkv, scatters q/k/v to [B,H,S,D],
//         scales q by 0.125.
// MODE 1: A=g_att (device global), B=w_out; epilogue adds b_out, writes to
//         out [BS, E].
// ---------------------------------------------------------------------------
template <int MODE>
__global__ __launch_bounds__(256) void sgemm_kernel(
    const float* __restrict__ A, const float* __restrict__ Bw,
    const float* __restrict__ bias, float* __restrict__ Cout,
    int M, int N, int K)
{
    __shared__ float As[8][128];
    __shared__ float Bs[8][128];

    // MODE 1 reads the attention scratch directly (host can't pass the
    // __device__ symbol address without an extra API call).
    const float* Abase = (MODE == 1) ? g_att : A;

    const int bx = blockIdx.x;   // N tile
    const int by = blockIdx.y;   // M tile
    const int t  = threadIdx.x;
    const int tx = t & 15;       // 0..15
    const int ty = t >> 4;       // 0..15

    // A loader: each thread one float4. 128 rows x 8 k -> 256 float4.
    const int a_row = t >> 1;
    const int a_k4  = (t & 1) * 4;
    // B loader: 8 rows x 128 cols -> 256 float4.
    const int b_row = t >> 5;
    const int b_c4  = (t & 31) * 4;

    const float* Aptr = Abase + (size_t)(by * 128 + a_row) * K + a_k4;
    const float* Bptr = Bw + (size_t)b_row * N + bx * 128 + b_c4;

    float acc[8][8];
#pragma unroll
    for (int i = 0; i < 8; i++)
#pragma unroll
        for (int j = 0; j < 8; j++) acc[i][j] = 0.0f;

    float4 av = *(const float4*)(Aptr);
    float4 bv = *(const float4*)(Bptr);

    for (int k0 = 0; k0 < K; k0 += 8) {
        // store staged tile
        As[a_k4 + 0][a_row] = av.x;
        As[a_k4 + 1][a_row] = av.y;
        As[a_k4 + 2][a_row] = av.z;
        As[a_k4 + 3][a_row] = av.w;
        *(float4*)&Bs[b_row][b_c4] = bv;
        __syncthreads();

        // prefetch next tile
        if (k0 + 8 < K) {
            av = *(const float4*)(Aptr + k0 + 8);
            bv = *(const float4*)(Bptr + (size_t)(k0 + 8) * N);
        }

#pragma unroll
        for (int kk = 0; kk < 8; kk++) {
            float af[8], bf[8];
            *(float4*)(af)     = *(const float4*)&As[kk][ty * 8];
            *(float4*)(af + 4) = *(const float4*)&As[kk][ty * 8 + 4];
            *(float4*)(bf)     = *(const float4*)&Bs[kk][tx * 8];
            *(float4*)(bf + 4) = *(const float4*)&Bs[kk][tx * 8 + 4];
#pragma unroll
            for (int i = 0; i < 8; i++)
#pragma unroll
                for (int j = 0; j < 8; j++)
                    acc[i][j] = fmaf(af[i], bf[j], acc[i][j]);
        }
        __syncthreads();
    }

    if (MODE == 0) {
        // scatter qkv: col in [0,3072). part constant per block (128 | 1024).
        const int part = (bx * 128) >> 10;
        float* dst = (part == 0) ? g_q : (part == 1) ? g_k : g_v;
        const float mult = (part == 0) ? 0.125f : 1.0f;
#pragma unroll
        for (int i = 0; i < 8; i++) {
            const int row = by * 128 + ty * 8 + i;
            const int b = row >> 11;       // /2048
            const int s = row & 2047;
#pragma unroll
            for (int j = 0; j < 8; j++) {
                const int col = bx * 128 + tx * 8 + j;
                const int e = col & 1023;
                const int h = e >> 6;
                const int d = e & 63;
                dst[(((b * HH) + h) * SS + s) * DD + d] =
                    (acc[i][j] + bias[col]) * mult;
            }
        }
    } else {
#pragma unroll
        for (int i = 0; i < 8; i++) {
            const int row = by * 128 + ty * 8 + i;
#pragma unroll
            for (int j = 0; j < 8; j++) {
                const int col = bx * 128 + tx * 8 + j;
                Cout[(size_t)row * EE + col] = acc[i][j] + bias[col];
            }
        }
    }
}

// ---------------------------------------------------------------------------
// Flash attention fp32. Block = 256 threads, one (64-query tile, b*h) pair.
// Online softmax over 32 KV tiles of 64. Q pre-scaled by 1/sqrt(D).
// ---------------------------------------------------------------------------
#define FA_PAD 65
#define FA_SMEM (4 * 64 * FA_PAD * 4)   // 66560 bytes

__global__ __launch_bounds__(256) void flash_attn_kernel()
{
    extern __shared__ float sm[];
    float* Qs = sm;                    // [64][FA_PAD]
    float* Ks = Qs + 64 * FA_PAD;
    float* Vs = Ks + 64 * FA_PAD;
    float* Ps = Vs + 64 * FA_PAD;

    const int qt = blockIdx.x;         // 0..31
    const int bh = blockIdx.y;         // 0..63
    const int t  = threadIdx.x;
    const int tx = t & 15;
    const int ty = t >> 4;

    const float* qbase = g_q + ((size_t)bh * SS + qt * 64) * DD;
    const float* kbase = g_k + (size_t)bh * SS * DD;
    const float* vbase = g_v + (size_t)bh * SS * DD;

    // Load Q tile [64,64]
#pragma unroll
    for (int i = 0; i < 4; i++) {
        const int lin = t + 256 * i;         // float4 index
        const int row = lin >> 4;
        const int c4  = (lin & 15) * 4;
        float4 v4 = *(const float4*)(qbase + row * 64 + c4);
        float* p = &Qs[row * FA_PAD + c4];
        p[0] = v4.x; p[1] = v4.y; p[2] = v4.z; p[3] = v4.w;
    }

    float m[4], l[4], o[4][4];
#pragma unroll
    for (int i = 0; i < 4; i++) {
        m[i] = -1e30f; l[i] = 0.0f;
#pragma unroll
        for (int j = 0; j < 4; j++) o[i][j] = 0.0f;
    }

    for (int kt = 0; kt < SS / 64; kt++) {
        const float* kb = kbase + (size_t)kt * 64 * DD;
        const float* vb = vbase + (size_t)kt * 64 * DD;
#pragma unroll
        for (int i = 0; i < 4; i++) {
            const int lin = t + 256 * i;
            const int row = lin >> 4;
            const int c4  = (lin & 15) * 4;
            float4 kv4 = *(const float4*)(kb + row * 64 + c4);
            float* p = &Ks[row * FA_PAD + c4];
            p[0] = kv4.x; p[1] = kv4.y; p[2] = kv4.z; p[3] = kv4.w;
            float4 vv4 = *(const float4*)(vb + row * 64 + c4);
            float* pv = &Vs[row * FA_PAD + c4];
            pv[0] = vv4.x; pv[1] = vv4.y; pv[2] = vv4.z; pv[3] = vv4.w;
        }
        __syncthreads();

        // S = Q K^T (thread: 4 q-rows x 4 k-cols)
        float s[4][4];
#pragma unroll
        for (int i = 0; i < 4; i++)
#pragma unroll
            for (int j = 0; j < 4; j++) s[i][j] = 0.0f;

#pragma unroll 8
        for (int kk = 0; kk < 64; kk++) {
            float qf[4], kf[4];
#pragma unroll
            for (int i = 0; i < 4; i++) qf[i] = Qs[(ty * 4 + i) * FA_PAD + kk];
#pragma unroll
            for (int j = 0; j < 4; j++) kf[j] = Ks[(tx * 4 + j) * FA_PAD + kk];
#pragma unroll
            for (int i = 0; i < 4; i++)
#pragma unroll
                for (int j = 0; j < 4; j++)
                    s[i][j] = fmaf(qf[i], kf[j], s[i][j]);
        }

        // online softmax per q-row (reduce across the 16 tx lanes)
#pragma unroll
        for (int i = 0; i < 4; i++) {
            float rm = fmaxf(fmaxf(s[i][0], s[i][1]), fmaxf(s[i][2], s[i][3]));
            rm = fmaxf(rm, __shfl_xor_sync(0xffffffffu, rm, 1));
            rm = fmaxf(rm, __shfl_xor_sync(0xffffffffu, rm, 2));
            rm = fmaxf(rm, __shfl_xor_sync(0xffffffffu, rm, 4));
            rm = fmaxf(rm, __shfl_xor_sync(0xffffffffu, rm, 8));
            const float nm = fmaxf(m[i], rm);
            float p0 = __expf(s[i][0] - nm);
            float p1 = __expf(s[i][1] - nm);
            float p2 = __expf(s[i][2] - nm);
            float p3 = __expf(s[i][3] - nm);
            float rs = p0 + p1 + p2 + p3;
            rs += __shfl_xor_sync(0xffffffffu, rs, 1);
            rs += __shfl_xor_sync(0xffffffffu, rs, 2);
            rs += __shfl_xor_sync(0xffffffffu, rs, 4);
            rs += __shfl_xor_sync(0xffffffffu, rs, 8);
            const float alpha = __expf(m[i] - nm);
            l[i] = l[i] * alpha + rs;
            m[i] = nm;
#pragma unroll
            for (int j = 0; j < 4; j++) o[i][j] *= alpha;
            float* prow = &Ps[(ty * 4 + i) * FA_PAD + tx * 4];
            prow[0] = p0; prow[1] = p1; prow[2] = p2; prow[3] = p3;
        }
        __syncthreads();

        // O += P V (thread: 4 q-rows x 4 d-cols)
#pragma unroll 8
        for (int kk = 0; kk < 64; kk++) {
            float pf[4], vf[4];
#pragma unroll
            for (int i = 0; i < 4; i++) pf[i] = Ps[(ty * 4 + i) * FA_PAD + kk];
#pragma unroll
            for (int j = 0; j < 4; j++) vf[j] = Vs[kk * FA_PAD + tx * 4 + j];
#pragma unroll
            for (int i = 0; i < 4; i++)
#pragma unroll
                for (int j = 0; j < 4; j++)
                    o[i][j] = fmaf(pf[i], vf[j], o[i][j]);
        }
        __syncthreads();
    }

    // Epilogue: normalize and write to [B,S,E]
    const int b = bh >> 4;
    const int h = bh & 15;
#pragma unroll
    for (int i = 0; i < 4; i++) {
        const int srow = qt * 64 + ty * 4 + i;
        const float inv = 1.0f / l[i];
        float* drow = g_att + ((size_t)b * SS + srow) * EE + h * DD + tx * 4;
#pragma unroll
        for (int j = 0; j < 4; j++) drow[j] = o[i][j] * inv;
    }
}

// ---------------------------------------------------------------------------
extern "C" void kernel_launch(void* const* d_in, const int* in_sizes, int n_in,
                              void* d_out, int out_size)
{
    const float* x     = (const float*)d_in[0];
    const float* w_qkv = (const float*)d_in[1];
    const float* b_qkv = (const float*)d_in[2];
    const float* w_out = (const float*)d_in[3];
    const float* b_out = (const float*)d_in[4];
    float* out = (float*)d_out;

    (void)in_sizes; (void)n_in; (void)out_size;

    cudaFuncSetAttribute(flash_attn_kernel,
                         cudaFuncAttributeMaxDynamicSharedMemorySize, FA_SMEM);

    // 1) QKV projection + scatter
    {
        dim3 grid(N_QKV / 128, BS / 128);   // (24, 64)
        sgemm_kernel<0><<<grid, 256>>>(x, w_qkv, b_qkv, nullptr,
                                       BS, N_QKV, CC);
    }
    // 2) Attention
    {
        dim3 grid(SS / 64, BB * HH);        // (32, 64)
        flash_attn_kernel<<<grid, 256, FA_SMEM>>>();
    }
    // 3) Output projection (reads g_att internally)
    {
        dim3 grid(EE / 128, BS / 128);      // (8, 64)
        sgemm_kernel<1><<<grid, 256>>>(nullptr, w_out, b_out, out,
                                       BS, EE, CC);
    }
}

// round 5
// speedup vs baseline: 1.1342x; 1.1342x over previous
#include <cuda_runtime.h>
#include <cuda_bf16.h>
#include <cstdint>

// Problem constants
#define BB 4
#define SS 2048
#define CC 1024
#define EE 1024
#define HH 16
#define DD 64
#define BS (BB * SS)        // 8192
#define N_QKV (3 * EE)      // 3072

// Scratch (static device globals — no runtime allocation allowed)
__device__ float g_q[BB * HH * SS * DD];   // [B,H,S,D], pre-scaled by 1/sqrt(D)
__device__ float g_k[BB * HH * SS * DD];
__device__ float g_v[BB * HH * SS * DD];
__device__ float g_att[BS * EE];           // [B,S,E] attention output

// ---------------------------------------------------------------------------
// Helpers: tf32 convert (round-to-nearest) + m16n8k8 tf32 mma
// ---------------------------------------------------------------------------
__device__ __forceinline__ unsigned f2tf(float x) {
    unsigned u;
    asm("cvt.rna.tf32.f32 %0, %1;" : "=r"(u) : "f"(x));
    return u;
}

__device__ __forceinline__ void mma_tf32(float* d, const unsigned* a,
                                         const unsigned* b) {
    asm volatile(
        "mma.sync.aligned.m16n8k8.row.col.f32.tf32.tf32.f32 "
        "{%0,%1,%2,%3}, {%4,%5,%6,%7}, {%8,%9}, {%0,%1,%2,%3};"
        : "+f"(d[0]), "+f"(d[1]), "+f"(d[2]), "+f"(d[3])
        : "r"(a[0]), "r"(a[1]), "r"(a[2]), "r"(a[3]), "r"(b[0]), "r"(b[1]));
}

// ---------------------------------------------------------------------------
// Split-tf32 GEMM: C = A @ B (+bias). fp32 accuracy via AhBh + AlBh + AhBl.
// Block tile 128x128, BK=32, 256 threads (8 warps, warp tile 64x32).
// MODE 0: A=x, B=w_qkv -> scatter q/k/v to [B,H,S,D], q scaled by 0.125.
// MODE 1: A=g_att,   B=w_out -> out [BS, E].
// ---------------------------------------------------------------------------
#define ASTR 132            // smem stride for A tiles (k-major): 4 mod 32
#define BSTR 136            // smem stride for B tiles: 8 mod 32
#define GEMM_SMEM ((32 * ASTR * 2 + 32 * BSTR * 2) * 4)   // 68608 B

template <int MODE>
__global__ __launch_bounds__(256) void tf32_gemm(
    const float* __restrict__ A, const float* __restrict__ Bw,
    const float* __restrict__ bias, float* __restrict__ Cout,
    int M, int N, int K)
{
    extern __shared__ float sm[];
    float* a_hi = sm;                       // [32][ASTR]  (k, m)
    float* a_lo = a_hi + 32 * ASTR;
    float* b_hi = a_lo + 32 * ASTR;         // [32][BSTR]  (k, n)
    float* b_lo = b_hi + 32 * BSTR;

    const float* Abase = (MODE == 1) ? g_att : A;

    const int bx = blockIdx.x, by = blockIdx.y;
    const int t = threadIdx.x;
    const int lane = t & 31;
    const int warp = t >> 5;
    const int wm = warp & 1;                // 0..1  (64-row blocks)
    const int wn = warp >> 1;               // 0..3  (32-col blocks)
    const int lr = lane >> 2;               // 0..7
    const int lt = lane & 3;                // 0..3

    // A loader: thread owns row a_m, k-offsets 4*(t>>7) + 8i (+j)
    const int a_m = t & 127;
    const int a_kb = (t >> 7) * 4;
    // B loader: thread owns col block c4, k-rows (t>>5) + 8i
    const int b_kb = t >> 5;
    const int b_c4 = (t & 31) * 4;

    const float* Ag = Abase + (size_t)(by * 128 + a_m) * K;
    const float* Bg = Bw + (size_t)(bx * 128 + b_c4);

    float acc[4][4][4];
#pragma unroll
    for (int mf = 0; mf < 4; mf++)
#pragma unroll
        for (int nf = 0; nf < 4; nf++)
#pragma unroll
            for (int r = 0; r < 4; r++) acc[mf][nf][r] = 0.0f;

    float4 av[4], bv[4];
#pragma unroll
    for (int i = 0; i < 4; i++) {
        av[i] = *(const float4*)(Ag + a_kb + 8 * i);
        bv[i] = *(const float4*)(Bg + (size_t)(b_kb + 8 * i) * N);
    }

    for (int k0 = 0; k0 < K; k0 += 32) {
        // store (with hi/lo split) to smem
#pragma unroll
        for (int i = 0; i < 4; i++) {
            const float* v = (const float*)&av[i];
#pragma unroll
            for (int j = 0; j < 4; j++) {
                const int kl = a_kb + 8 * i + j;
                float x = v[j];
                unsigned h = f2tf(x);
                float hf = __uint_as_float(h);
                a_hi[kl * ASTR + a_m] = hf;
                a_lo[kl * ASTR + a_m] = __uint_as_float(f2tf(x - hf));
            }
            const float* w = (const float*)&bv[i];
            const int kr = b_kb + 8 * i;
#pragma unroll
            for (int j = 0; j < 4; j++) {
                float x = w[j];
                unsigned h = f2tf(x);
                float hf = __uint_as_float(h);
                b_hi[kr * BSTR + b_c4 + j] = hf;
                b_lo[kr * BSTR + b_c4 + j] = __uint_as_float(f2tf(x - hf));
            }
        }
        __syncthreads();

        if (k0 + 32 < K) {
#pragma unroll
            for (int i = 0; i < 4; i++) {
                av[i] = *(const float4*)(Ag + k0 + 32 + a_kb + 8 * i);
                bv[i] = *(const float4*)(Bg + (size_t)(k0 + 32 + b_kb + 8 * i) * N);
            }
        }

#pragma unroll
        for (int ks = 0; ks < 4; ks++) {
            const int kk = ks * 8 + lt;
            unsigned ah[4][4], al[4][4];
#pragma unroll
            for (int mf = 0; mf < 4; mf++) {
                const int m0 = wm * 64 + mf * 16 + lr;
                ah[mf][0] = __float_as_uint(a_hi[kk * ASTR + m0]);
                ah[mf][1] = __float_as_uint(a_hi[kk * ASTR + m0 + 8]);
                ah[mf][2] = __float_as_uint(a_hi[(kk + 4) * ASTR + m0]);
                ah[mf][3] = __float_as_uint(a_hi[(kk + 4) * ASTR + m0 + 8]);
                al[mf][0] = __float_as_uint(a_lo[kk * ASTR + m0]);
                al[mf][1] = __float_as_uint(a_lo[kk * ASTR + m0 + 8]);
                al[mf][2] = __float_as_uint(a_lo[(kk + 4) * ASTR + m0]);
                al[mf][3] = __float_as_uint(a_lo[(kk + 4) * ASTR + m0 + 8]);
            }
            unsigned bh[4][2], bl[4][2];
#pragma unroll
            for (int nf = 0; nf < 4; nf++) {
                const int n0 = wn * 32 + nf * 8 + lr;
                bh[nf][0] = __float_as_uint(b_hi[kk * BSTR + n0]);
                bh[nf][1] = __float_as_uint(b_hi[(kk + 4) * BSTR + n0]);
                bl[nf][0] = __float_as_uint(b_lo[kk * BSTR + n0]);
                bl[nf][1] = __float_as_uint(b_lo[(kk + 4) * BSTR + n0]);
            }
#pragma unroll
            for (int mf = 0; mf < 4; mf++)
#pragma unroll
                for (int nf = 0; nf < 4; nf++) {
                    mma_tf32(acc[mf][nf], ah[mf], bh[nf]);
                    mma_tf32(acc[mf][nf], al[mf], bh[nf]);
                    mma_tf32(acc[mf][nf], ah[mf], bl[nf]);
                }
        }
        __syncthreads();
    }

    // Epilogue. c-frag: r0=(lr, 2*lt), r1=+1 col, r2=(lr+8, 2*lt), r3=+1.
    if (MODE == 0) {
        const int part = (bx * 128) >> 10;
        float* dst = (part == 0) ? g_q : (part == 1) ? g_k : g_v;
        const float mult = (part == 0) ? 0.125f : 1.0f;
#pragma unroll
        for (int nf = 0; nf < 4; nf++) {
            const int col = bx * 128 + wn * 32 + nf * 8 + 2 * lt;
            const float bi0 = bias[col], bi1 = bias[col + 1];
            const int e = col & 1023;
            const int h = e >> 6, d = e & 63;
#pragma unroll
            for (int mf = 0; mf < 4; mf++) {
#pragma unroll
                for (int half = 0; half < 2; half++) {
                    const int row = by * 128 + wm * 64 + mf * 16 + lr + half * 8;
                    const int b = row >> 11, s = row & 2047;
                    float2 v;
                    v.x = (acc[mf][nf][half * 2 + 0] + bi0) * mult;
                    v.y = (acc[mf][nf][half * 2 + 1] + bi1) * mult;
                    *(float2*)&dst[(((size_t)(b * HH + h)) * SS + s) * DD + d] = v;
                }
            }
        }
    } else {
#pragma unroll
        for (int nf = 0; nf < 4; nf++) {
            const int col = bx * 128 + wn * 32 + nf * 8 + 2 * lt;
            const float bi0 = bias[col], bi1 = bias[col + 1];
#pragma unroll
            for (int mf = 0; mf < 4; mf++) {
#pragma unroll
                for (int half = 0; half < 2; half++) {
                    const int row = by * 128 + wm * 64 + mf * 16 + lr + half * 8;
                    float2 v;
                    v.x = acc[mf][nf][half * 2 + 0] + bi0;
                    v.y = acc[mf][nf][half * 2 + 1] + bi1;
                    *(float2*)&Cout[(size_t)row * EE + col] = v;
                }
            }
        }
    }
}

// ---------------------------------------------------------------------------
// Flash attention, tf32 tensor cores. Block = 256 threads (8 warps), q-tile
// 128 (16 rows per warp), kv-tile 64, online softmax in registers on the
// mma C-fragment layout. P re-enters the A-fragment layout via smem.
// ---------------------------------------------------------------------------
#define QSTR 68   // 4 mod 32 : conflict-free for (8-row x 4-col) frag loads
#define KSTR 68
#define VSTR 72   // 8 mod 32 : conflict-free for (4-row x 8-col) frag loads
#define FA_SMEM ((128 * QSTR + 128 * QSTR + 64 * KSTR + 64 * VSTR) * 4) // 105472

__global__ __launch_bounds__(256, 2) void fa_tf32()
{
    extern __shared__ float sm[];
    float* Qs = sm;                          // [128][QSTR]
    float* Ps = Qs + 128 * QSTR;             // [128][QSTR]
    float* Ks = Ps + 128 * QSTR;             // [64][KSTR]  (seq, d)
    float* Vs = Ks + 64 * KSTR;              // [64][VSTR]  (seq, d)

    const int qt = blockIdx.x;               // 0..15
    const int bh = blockIdx.y;               // 0..63
    const int t = threadIdx.x;
    const int lane = t & 31;
    const int warp = t >> 5;
    const int lr = lane >> 2;                // 0..7
    const int lt = lane & 3;                 // 0..3

    const float* qbase = g_q + ((size_t)bh * SS + qt * 128) * DD;
    const float* kbase = g_k + (size_t)bh * SS * DD;
    const float* vbase = g_v + (size_t)bh * SS * DD;

    // Stage Q tile [128][64] -> Qs (tf32-rounded), once.
    {
        const int row0 = t >> 4;             // + 16*i
        const int c4 = (t & 15) * 4;
#pragma unroll
        for (int i = 0; i < 8; i++) {
            const int row = row0 + 16 * i;
            float4 v = *(const float4*)(qbase + row * DD + c4);
            float* p = &Qs[row * QSTR + c4];
            p[0] = __uint_as_float(f2tf(v.x));
            p[1] = __uint_as_float(f2tf(v.y));
            p[2] = __uint_as_float(f2tf(v.z));
            p[3] = __uint_as_float(f2tf(v.w));
        }
    }
    __syncthreads();

    float m0 = -1e30f, m1 = -1e30f, l0 = 0.0f, l1 = 0.0f;
    float o[8][4];
#pragma unroll
    for (int nf = 0; nf < 8; nf++)
#pragma unroll
        for (int r = 0; r < 4; r++) o[nf][r] = 0.0f;

    const int qrow = warp * 16;              // warp's row block in tile

    for (int kt = 0; kt < SS / 64; kt++) {
        __syncthreads();
        // Load K, V tiles [64][64] (tf32-rounded)
        {
            const int row0 = t >> 4;         // + 16*i
            const int c4 = (t & 15) * 4;
            const float* kb = kbase + (size_t)kt * 64 * DD;
            const float* vb = vbase + (size_t)kt * 64 * DD;
#pragma unroll
            for (int i = 0; i < 4; i++) {
                const int row = row0 + 16 * i;
                float4 kv = *(const float4*)(kb + row * DD + c4);
                float* pk = &Ks[row * KSTR + c4];
                pk[0] = __uint_as_float(f2tf(kv.x));
                pk[1] = __uint_as_float(f2tf(kv.y));
                pk[2] = __uint_as_float(f2tf(kv.z));
                pk[3] = __uint_as_float(f2tf(kv.w));
                float4 vv = *(const float4*)(vb + row * DD + c4);
                float* pv = &Vs[row * VSTR + c4];
                pv[0] = __uint_as_float(f2tf(vv.x));
                pv[1] = __uint_as_float(f2tf(vv.y));
                pv[2] = __uint_as_float(f2tf(vv.z));
                pv[3] = __uint_as_float(f2tf(vv.w));
            }
        }
        __syncthreads();

        // S = Q K^T  (m16 x n64, k=64)
        float s[8][4];
#pragma unroll
        for (int nf = 0; nf < 8; nf++)
#pragma unroll
            for (int r = 0; r < 4; r++) s[nf][r] = 0.0f;

#pragma unroll
        for (int ks = 0; ks < 8; ks++) {
            const int kk = ks * 8 + lt;
            unsigned qa[4];
            qa[0] = __float_as_uint(Qs[(qrow + lr) * QSTR + kk]);
            qa[1] = __float_as_uint(Qs[(qrow + lr + 8) * QSTR + kk]);
            qa[2] = __float_as_uint(Qs[(qrow + lr) * QSTR + kk + 4]);
            qa[3] = __float_as_uint(Qs[(qrow + lr + 8) * QSTR + kk + 4]);
#pragma unroll
            for (int nf = 0; nf < 8; nf++) {
                unsigned kb2[2];
                kb2[0] = __float_as_uint(Ks[(nf * 8 + lr) * KSTR + kk]);
                kb2[1] = __float_as_uint(Ks[(nf * 8 + lr) * KSTR + kk + 4]);
                mma_tf32(s[nf], qa, kb2);
            }
        }

        // Online softmax (rows lr and lr+8; 4 lanes per row group)
        float rm0 = -1e30f, rm1 = -1e30f;
#pragma unroll
        for (int nf = 0; nf < 8; nf++) {
            rm0 = fmaxf(rm0, fmaxf(s[nf][0], s[nf][1]));
            rm1 = fmaxf(rm1, fmaxf(s[nf][2], s[nf][3]));
        }
        rm0 = fmaxf(rm0, __shfl_xor_sync(0xffffffffu, rm0, 1));
        rm0 = fmaxf(rm0, __shfl_xor_sync(0xffffffffu, rm0, 2));
        rm1 = fmaxf(rm1, __shfl_xor_sync(0xffffffffu, rm1, 1));
        rm1 = fmaxf(rm1, __shfl_xor_sync(0xffffffffu, rm1, 2));
        const float nm0 = fmaxf(m0, rm0), nm1 = fmaxf(m1, rm1);
        float rs0 = 0.0f, rs1 = 0.0f;
#pragma unroll
        for (int nf = 0; nf < 8; nf++) {
            float p0 = __expf(s[nf][0] - nm0);
            float p1 = __expf(s[nf][1] - nm0);
            float p2 = __expf(s[nf][2] - nm1);
            float p3 = __expf(s[nf][3] - nm1);
            rs0 += p0 + p1;
            rs1 += p2 + p3;
            float2 w0 = {__uint_as_float(f2tf(p0)), __uint_as_float(f2tf(p1))};
            float2 w1 = {__uint_as_float(f2tf(p2)), __uint_as_float(f2tf(p3))};
            *(float2*)&Ps[(qrow + lr) * QSTR + nf * 8 + 2 * lt] = w0;
            *(float2*)&Ps[(qrow + lr + 8) * QSTR + nf * 8 + 2 * lt] = w1;
        }
        rs0 += __shfl_xor_sync(0xffffffffu, rs0, 1);
        rs0 += __shfl_xor_sync(0xffffffffu, rs0, 2);
        rs1 += __shfl_xor_sync(0xffffffffu, rs1, 1);
        rs1 += __shfl_xor_sync(0xffffffffu, rs1, 2);
        const float al0 = __expf(m0 - nm0), al1 = __expf(m1 - nm1);
        l0 = l0 * al0 + rs0;
        l1 = l1 * al1 + rs1;
        m0 = nm0; m1 = nm1;
#pragma unroll
        for (int nf = 0; nf < 8; nf++) {
            o[nf][0] *= al0; o[nf][1] *= al0;
            o[nf][2] *= al1; o[nf][3] *= al1;
        }
        __syncwarp();

        // O += P V  (m16 x n64(d), k=64(seq))
#pragma unroll
        for (int ks = 0; ks < 8; ks++) {
            const int kk = ks * 8 + lt;
            unsigned pa[4];
            pa[0] = __float_as_uint(Ps[(qrow + lr) * QSTR + kk]);
            pa[1] = __float_as_uint(Ps[(qrow + lr + 8) * QSTR + kk]);
            pa[2] = __float_as_uint(Ps[(qrow + lr) * QSTR + kk + 4]);
            pa[3] = __float_as_uint(Ps[(qrow + lr + 8) * QSTR + kk + 4]);
#pragma unroll
            for (int nf = 0; nf < 8; nf++) {
                unsigned vb2[2];
                vb2[0] = __float_as_uint(Vs[kk * VSTR + nf * 8 + lr]);
                vb2[1] = __float_as_uint(Vs[(kk + 4) * VSTR + nf * 8 + lr]);
                mma_tf32(o[nf], pa, vb2);
            }
        }
    }

    // Epilogue: normalize and scatter to g_att [B,S,E]
    const int b = bh >> 4, h = bh & 15;
    const float inv0 = 1.0f / l0, inv1 = 1.0f / l1;
    const int srow0 = qt * 128 + qrow + lr;
    float* base0 = g_att + ((size_t)b * SS + srow0) * EE + h * DD;
    float* base1 = base0 + (size_t)8 * EE;
#pragma unroll
    for (int nf = 0; nf < 8; nf++) {
        float2 v0 = {o[nf][0] * inv0, o[nf][1] * inv0};
        float2 v1 = {o[nf][2] * inv1, o[nf][3] * inv1};
        *(float2*)(base0 + nf * 8 + 2 * lt) = v0;
        *(float2*)(base1 + nf * 8 + 2 * lt) = v1;
    }
}

// ---------------------------------------------------------------------------
extern "C" void kernel_launch(void* const* d_in, const int* in_sizes, int n_in,
                              void* d_out, int out_size)
{
    const float* x     = (const float*)d_in[0];
    const float* w_qkv = (const float*)d_in[1];
    const float* b_qkv = (const float*)d_in[2];
    const float* w_out = (const float*)d_in[3];
    const float* b_out = (const float*)d_in[4];
    float* out = (float*)d_out;

    (void)in_sizes; (void)n_in; (void)out_size;

    cudaFuncSetAttribute(tf32_gemm<0>,
                         cudaFuncAttributeMaxDynamicSharedMemorySize, GEMM_SMEM);
    cudaFuncSetAttribute(tf32_gemm<1>,
                         cudaFuncAttributeMaxDynamicSharedMemorySize, GEMM_SMEM);
    cudaFuncSetAttribute(fa_tf32,
                         cudaFuncAttributeMaxDynamicSharedMemorySize, FA_SMEM);

    // 1) QKV projection (split-tf32) + scatter
    {
        dim3 grid(N_QKV / 128, BS / 128);   // (24, 64)
        tf32_gemm<0><<<grid, 256, GEMM_SMEM>>>(x, w_qkv, b_qkv, nullptr,
                                               BS, N_QKV, CC);
    }
    // 2) Attention (plain tf32 tensor-core flash attention)
    {
        dim3 grid(SS / 128, BB * HH);       // (16, 64)
        fa_tf32<<<grid, 256, FA_SMEM>>>();
    }
    // 3) Output projection (split-tf32, reads g_att internally)
    {
        dim3 grid(EE / 128, BS / 128);      // (8, 64)
        tf32_gemm<1><<<grid, 256, GEMM_SMEM>>>(nullptr, w_out, b_out, out,
                                               BS, EE, CC);
    }
}

// round 7
// speedup vs baseline: 3.3058x; 2.9146x over previous
#include <cuda_runtime.h>
#include <cuda_bf16.h>
#include <cstdint>

// Problem constants
#define BB 4
#define SS 2048
#define CC 1024
#define EE 1024
#define HH 16
#define DD 64
#define BS (BB * SS)        // 8192
#define N_QKV (3 * EE)      // 3072

// f32 scratch
__device__ float g_q[BB * HH * SS * DD];   // [B,H,S,D], q pre-scaled by 1/8
__device__ float g_k[BB * HH * SS * DD];
__device__ float g_v[BB * HH * SS * DD];
__device__ float g_att[BS * EE];           // [B,S,E]

// bf16 split operands, pre-packed in mma-fragment order.
// A: per (m_tile 128, k_chunk 64): 16KB buffer laid out [ks(4)][mb(8)][lane(32)][16B]
//    where the 16B = regs {a0,a1,a2,a3} of mma.m16n8k16 for that lane.
// B: per (n_tile 128, k_chunk 64): 16KB buffer [ks(4)][nb(16)][lane(32)][8B]
//    where the 8B = regs {b0,b1}.
__device__ __nv_bfloat16 g_ah[BS * CC],     g_al[BS * CC];
__device__ __nv_bfloat16 g_wqh[CC * N_QKV], g_wql[CC * N_QKV];
__device__ __nv_bfloat16 g_woh[CC * EE],    g_wol[CC * EE];

// ---------------------------------------------------------------------------
// Helpers
// ---------------------------------------------------------------------------
__device__ __forceinline__ uint32_t smem_u32(const void* p) {
    uint32_t a;
    asm("{ .reg .u64 t; cvta.to.shared.u64 t, %1; cvt.u32.u64 %0, t; }"
        : "=r"(a) : "l"(p));
    return a;
}
__device__ __forceinline__ void cp16(uint32_t s, const void* gp) {
    uint64_t g;
    asm("cvta.to.global.u64 %0, %1;" : "=l"(g) : "l"(gp));
    asm volatile("cp.async.cg.shared.global [%0], [%1], 16;" :: "r"(s), "l"(g) : "memory");
}
__device__ __forceinline__ void mma_bf16(float* d, const uint32_t* a,
                                         const uint32_t* b) {
    asm volatile(
        "mma.sync.aligned.m16n8k16.row.col.f32.bf16.bf16.f32 "
        "{%0,%1,%2,%3}, {%4,%5,%6,%7}, {%8,%9}, {%0,%1,%2,%3};"
        : "+f"(d[0]), "+f"(d[1]), "+f"(d[2]), "+f"(d[3])
        : "r"(a[0]), "r"(a[1]), "r"(a[2]), "r"(a[3]), "r"(b[0]), "r"(b[1]));
}
__device__ __forceinline__ unsigned f2tf(float x) {
    unsigned u;
    asm("cvt.rna.tf32.f32 %0, %1;" : "=r"(u) : "f"(x));
    return u;
}
__device__ __forceinline__ void mma_tf32(float* d, const unsigned* a, const unsigned* b) {
    asm volatile(
        "mma.sync.aligned.m16n8k8.row.col.f32.tf32.tf32.f32 "
        "{%0,%1,%2,%3}, {%4,%5,%6,%7}, {%8,%9}, {%0,%1,%2,%3};"
        : "+f"(d[0]), "+f"(d[1]), "+f"(d[2]), "+f"(d[3])
        : "r"(a[0]), "r"(a[1]), "r"(a[2]), "r"(a[3]), "r"(b[0]), "r"(b[1]));
}
__device__ __forceinline__ unsigned pack_bf16_hi(float x, float y) {
    __nv_bfloat16 h0 = __float2bfloat16(x);
    __nv_bfloat16 h1 = __float2bfloat16(y);
    return (unsigned)__bfloat16_as_ushort(h0) |
           ((unsigned)__bfloat16_as_ushort(h1) << 16);
}
__device__ __forceinline__ unsigned pack_bf16_lo(float x, float y) {
    float hx = __bfloat162float(__float2bfloat16(x));
    float hy = __bfloat162float(__float2bfloat16(y));
    __nv_bfloat16 l0 = __float2bfloat16(x - hx);
    __nv_bfloat16 l1 = __float2bfloat16(y - hy);
    return (unsigned)__bfloat16_as_ushort(l0) |
           ((unsigned)__bfloat16_as_ushort(l1) << 16);
}

// ---------------------------------------------------------------------------
// Prep kernels: split fp32 into bf16 hi/lo, store in mma-fragment order.
// Each thread handles one (row, even-k) pair -> one packed 32-bit word
// (elements k, k+1 share a fragment register).
// ---------------------------------------------------------------------------
// A source [M][1024] row-major. SRC 0: x param; SRC 1: g_att.
template <int SRC>
__global__ __launch_bounds__(256) void prep_a(const float* __restrict__ xin)
{
    const float* src = (SRC == 1) ? g_att : xin;
    const int idx = blockIdx.x * 256 + threadIdx.x;   // < BS*512
    const int m = idx >> 9;
    const int kp = idx & 511;
    const int k = kp * 2;
    float2 v = *(const float2*)(src + (size_t)m * CC + k);

    const int mt = m >> 7, mr = m & 127;
    const int kc = k >> 6, kl6 = k & 63;
    const int ks = kl6 >> 4, kl = kl6 & 15;
    const int mb = mr >> 4, r = mr & 15;
    const int lane = (r & 7) * 4 + ((kl & 7) >> 1);
    const int reg = (r >> 3) + 2 * (kl >> 3);
    const size_t byte = (size_t)(mt * 16 + kc) * 16384 +
                        (size_t)((ks * 8 + mb) * 32 + lane) * 16 + reg * 4;
    *(unsigned*)((char*)g_ah + byte) = pack_bf16_hi(v.x, v.y);
    *(unsigned*)((char*)g_al + byte) = pack_bf16_lo(v.x, v.y);
}

// B source w [1024][N] row-major -> fragment tiles over transposed [n][k].
template <int MODE>   // 0: w_qkv (N=3072), 1: w_out (N=1024)
__global__ __launch_bounds__(256) void prep_b(const float* __restrict__ w)
{
    constexpr int N = (MODE == 0) ? N_QKV : EE;
    const int idx = blockIdx.x * 256 + threadIdx.x;   // < 512*N
    const int kp = idx / N;
    const int n = idx - kp * N;
    const int k = kp * 2;
    const float w0 = w[(size_t)k * N + n];
    const float w1 = w[(size_t)(k + 1) * N + n];

    const int nt = n >> 7, nr = n & 127;
    const int kc = k >> 6, kl6 = k & 63;
    const int ks = kl6 >> 4, kl = kl6 & 15;
    const int nb = nr >> 3, gr = nr & 7;
    const int lane = gr * 4 + ((kl & 7) >> 1);
    const int reg = kl >> 3;
    const size_t byte = (size_t)(nt * 16 + kc) * 16384 +
                        (size_t)((ks * 16 + nb) * 32 + lane) * 8 + reg * 4;
    if (MODE == 0) {
        *(unsigned*)((char*)g_wqh + byte) = pack_bf16_hi(w0, w1);
        *(unsigned*)((char*)g_wql + byte) = pack_bf16_lo(w0, w1);
    } else {
        *(unsigned*)((char*)g_woh + byte) = pack_bf16_hi(w0, w1);
        *(unsigned*)((char*)g_wol + byte) = pack_bf16_lo(w0, w1);
    }
}

// ---------------------------------------------------------------------------
// Split-bf16 HMMA GEMM. CTA tile 128x128, K in 16 chunks of 64, 256 threads
// (8 warps, warp tile 64x32). Double-buffered cp.async (2 x 64KB stages).
// Fragments load as LDS.128 (A) / LDS.64 (B), conflict-free.
// MODE 0: +b_qkv, scatter q/k/v (q * 0.125).  MODE 1: +b_out -> Cout.
// ---------------------------------------------------------------------------
#define GEMM_SMEM (2 * 65536)

template <int MODE>
__global__ __launch_bounds__(256, 1) void bf16_gemm(
    const float* __restrict__ bias, float* __restrict__ Cout)
{
    extern __shared__ __align__(128) char tsm[];
    const uint32_t sbase = smem_u32(tsm);

    const int t = threadIdx.x;
    const int lane = t & 31;
    const int warp = t >> 5;
    const int wm = warp & 1;     // 0..1  (64-row block)
    const int wn = warp >> 1;    // 0..3  (32-col block)
    const int lr = lane >> 2;
    const int lt = lane & 3;
    const int bx = blockIdx.x, by = blockIdx.y;

    const char* Ah = (const char*)g_ah;
    const char* Al = (const char*)g_al;
    const char* Bh = (MODE == 0) ? (const char*)g_wqh : (const char*)g_woh;
    const char* Bl = (MODE == 0) ? (const char*)g_wql : (const char*)g_wol;
    const size_t aoff = (size_t)by * 16 * 16384;
    const size_t boff = (size_t)bx * 16 * 16384;

    float acc[4][4][4];
#pragma unroll
    for (int mf = 0; mf < 4; mf++)
#pragma unroll
        for (int nf = 0; nf < 4; nf++)
#pragma unroll
            for (int r = 0; r < 4; r++) acc[mf][nf][r] = 0.0f;

    // stage layout: Ahi @0, Alo @16K, Bhi @32K, Blo @48K
    auto issue = [&](int c) {
        const uint32_t sdst = sbase + (c & 1) * 65536;
        const char* ga0 = Ah + aoff + (size_t)c * 16384;
        const char* ga1 = Al + aoff + (size_t)c * 16384;
        const char* gb0 = Bh + boff + (size_t)c * 16384;
        const char* gb1 = Bl + boff + (size_t)c * 16384;
#pragma unroll
        for (int i = 0; i < 4; i++) {
            const int o = (t + i * 256) * 16;
            cp16(sdst + o,         ga0 + o);
            cp16(sdst + 16384 + o, ga1 + o);
            cp16(sdst + 32768 + o, gb0 + o);
            cp16(sdst + 49152 + o, gb1 + o);
        }
        asm volatile("cp.async.commit_group;" ::: "memory");
    };

    issue(0);
    for (int c = 0; c < 16; ++c) {
        if (c + 1 < 16) {
            issue(c + 1);
            asm volatile("cp.async.wait_group 1;" ::: "memory");
        } else {
            asm volatile("cp.async.wait_group 0;" ::: "memory");
        }
        __syncthreads();

        const char* sa = tsm + (c & 1) * 65536;
#pragma unroll
        for (int ks = 0; ks < 4; ks++) {
            uint4 ah[4], al[4];
#pragma unroll
            for (int mf = 0; mf < 4; mf++) {
                const int off = ((ks * 8 + wm * 4 + mf) * 32 + lane) * 16;
                ah[mf] = *(const uint4*)(sa + off);
                al[mf] = *(const uint4*)(sa + 16384 + off);
            }
            uint2 bh[4], bl[4];
#pragma unroll
            for (int nf = 0; nf < 4; nf++) {
                const int off = ((ks * 16 + wn * 4 + nf) * 32 + lane) * 8;
                bh[nf] = *(const uint2*)(sa + 32768 + off);
                bl[nf] = *(const uint2*)(sa + 49152 + off);
            }
#pragma unroll
            for (int mf = 0; mf < 4; mf++)
#pragma unroll
                for (int nf = 0; nf < 4; nf++) {
                    mma_bf16(acc[mf][nf], &ah[mf].x, &bh[nf].x);
                    mma_bf16(acc[mf][nf], &al[mf].x, &bh[nf].x);
                    mma_bf16(acc[mf][nf], &ah[mf].x, &bl[nf].x);
                }
        }
        __syncthreads();
    }

    // Epilogue. c-frag: r0=(lr, 2lt), r1=+1 col, r2=(lr+8, 2lt), r3=+1.
    if (MODE == 0) {
        const int part = bx >> 3;
        float* dst = (part == 0) ? g_q : (part == 1) ? g_k : g_v;
        const float mult = (part == 0) ? 0.125f : 1.0f;
#pragma unroll
        for (int nf = 0; nf < 4; nf++) {
            const int col = bx * 128 + wn * 32 + nf * 8 + 2 * lt;
            const float bi0 = bias[col], bi1 = bias[col + 1];
            const int e = col & 1023;
            const int h = e >> 6, d = e & 63;
#pragma unroll
            for (int mf = 0; mf < 4; mf++) {
#pragma unroll
                for (int half = 0; half < 2; half++) {
                    const int row = by * 128 + wm * 64 + mf * 16 + lr + half * 8;
                    const int b = row >> 11, s = row & 2047;
                    float2 v;
                    v.x = (acc[mf][nf][half * 2 + 0] + bi0) * mult;
                    v.y = (acc[mf][nf][half * 2 + 1] + bi1) * mult;
                    *(float2*)&dst[(((size_t)(b * HH + h)) * SS + s) * DD + d] = v;
                }
            }
        }
    } else {
#pragma unroll
        for (int nf = 0; nf < 4; nf++) {
            const int col = bx * 128 + wn * 32 + nf * 8 + 2 * lt;
            const float bi0 = bias[col], bi1 = bias[col + 1];
#pragma unroll
            for (int mf = 0; mf < 4; mf++) {
#pragma unroll
                for (int half = 0; half < 2; half++) {
                    const int row = by * 128 + wm * 64 + mf * 16 + lr + half * 8;
                    float2 v;
                    v.x = acc[mf][nf][half * 2 + 0] + bi0;
                    v.y = acc[mf][nf][half * 2 + 1] + bi1;
                    *(float2*)&Cout[(size_t)row * EE + col] = v;
                }
            }
        }
    }
}

// ---------------------------------------------------------------------------
// Flash attention, tf32 HMMA (unchanged from R5; next round's target).
// ---------------------------------------------------------------------------
#define QSTR 68
#define KSTR 68
#define VSTR 72
#define FA_SMEM ((128 * QSTR + 128 * QSTR + 64 * KSTR + 64 * VSTR) * 4)

__global__ __launch_bounds__(256, 2) void fa_tf32()
{
    extern __shared__ float sm[];
    float* Qs = sm;
    float* Ps = Qs + 128 * QSTR;
    float* Ks = Ps + 128 * QSTR;
    float* Vs = Ks + 64 * KSTR;

    const int qt = blockIdx.x;
    const int bh = blockIdx.y;
    const int t = threadIdx.x;
    const int lane = t & 31;
    const int warp = t >> 5;
    const int lr = lane >> 2;
    const int lt = lane & 3;

    const float* qbase = g_q + ((size_t)bh * SS + qt * 128) * DD;
    const float* kbase = g_k + (size_t)bh * SS * DD;
    const float* vbase = g_v + (size_t)bh * SS * DD;

    {
        const int row0 = t >> 4;
        const int c4 = (t & 15) * 4;
#pragma unroll
        for (int i = 0; i < 8; i++) {
            const int row = row0 + 16 * i;
            float4 v = *(const float4*)(qbase + row * DD + c4);
            float* p = &Qs[row * QSTR + c4];
            p[0] = __uint_as_float(f2tf(v.x));
            p[1] = __uint_as_float(f2tf(v.y));
            p[2] = __uint_as_float(f2tf(v.z));
            p[3] = __uint_as_float(f2tf(v.w));
        }
    }
    __syncthreads();

    float m0 = -1e30f, m1 = -1e30f, l0 = 0.0f, l1 = 0.0f;
    float o[8][4];
#pragma unroll
    for (int nf = 0; nf < 8; nf++)
#pragma unroll
        for (int r = 0; r < 4; r++) o[nf][r] = 0.0f;

    const int qrow = warp * 16;

    for (int kt = 0; kt < SS / 64; kt++) {
        __syncthreads();
        {
            const int row0 = t >> 4;
            const int c4 = (t & 15) * 4;
            const float* kb = kbase + (size_t)kt * 64 * DD;
            const float* vb = vbase + (size_t)kt * 64 * DD;
#pragma unroll
            for (int i = 0; i < 4; i++) {
                const int row = row0 + 16 * i;
                float4 kv = *(const float4*)(kb + row * DD + c4);
                float* pk = &Ks[row * KSTR + c4];
                pk[0] = __uint_as_float(f2tf(kv.x));
                pk[1] = __uint_as_float(f2tf(kv.y));
                pk[2] = __uint_as_float(f2tf(kv.z));
                pk[3] = __uint_as_float(f2tf(kv.w));
                float4 vv = *(const float4*)(vb + row * DD + c4);
                float* pv = &Vs[row * VSTR + c4];
                pv[0] = __uint_as_float(f2tf(vv.x));
                pv[1] = __uint_as_float(f2tf(vv.y));
                pv[2] = __uint_as_float(f2tf(vv.z));
                pv[3] = __uint_as_float(f2tf(vv.w));
            }
        }
        __syncthreads();

        float s[8][4];
#pragma unroll
        for (int nf = 0; nf < 8; nf++)
#pragma unroll
            for (int r = 0; r < 4; r++) s[nf][r] = 0.0f;

#pragma unroll
        for (int ks = 0; ks < 8; ks++) {
            const int kk = ks * 8 + lt;
            unsigned qa[4];
            qa[0] = __float_as_uint(Qs[(qrow + lr) * QSTR + kk]);
            qa[1] = __float_as_uint(Qs[(qrow + lr + 8) * QSTR + kk]);
            qa[2] = __float_as_uint(Qs[(qrow + lr) * QSTR + kk + 4]);
            qa[3] = __float_as_uint(Qs[(qrow + lr + 8) * QSTR + kk + 4]);
#pragma unroll
            for (int nf = 0; nf < 8; nf++) {
                unsigned kb2[2];
                kb2[0] = __float_as_uint(Ks[(nf * 8 + lr) * KSTR + kk]);
                kb2[1] = __float_as_uint(Ks[(nf * 8 + lr) * KSTR + kk + 4]);
                mma_tf32(s[nf], qa, kb2);
            }
        }

        float rm0 = -1e30f, rm1 = -1e30f;
#pragma unroll
        for (int nf = 0; nf < 8; nf++) {
            rm0 = fmaxf(rm0, fmaxf(s[nf][0], s[nf][1]));
            rm1 = fmaxf(rm1, fmaxf(s[nf][2], s[nf][3]));
        }
        rm0 = fmaxf(rm0, __shfl_xor_sync(0xffffffffu, rm0, 1));
        rm0 = fmaxf(rm0, __shfl_xor_sync(0xffffffffu, rm0, 2));
        rm1 = fmaxf(rm1, __shfl_xor_sync(0xffffffffu, rm1, 1));
        rm1 = fmaxf(rm1, __shfl_xor_sync(0xffffffffu, rm1, 2));
        const float nm0 = fmaxf(m0, rm0), nm1 = fmaxf(m1, rm1);
        float rs0 = 0.0f, rs1 = 0.0f;
#pragma unroll
        for (int nf = 0; nf < 8; nf++) {
            float p0 = __expf(s[nf][0] - nm0);
            float p1 = __expf(s[nf][1] - nm0);
            float p2 = __expf(s[nf][2] - nm1);
            float p3 = __expf(s[nf][3] - nm1);
            rs0 += p0 + p1;
            rs1 += p2 + p3;
            float2 w0 = {__uint_as_float(f2tf(p0)), __uint_as_float(f2tf(p1))};
            float2 w1 = {__uint_as_float(f2tf(p2)), __uint_as_float(f2tf(p3))};
            *(float2*)&Ps[(qrow + lr) * QSTR + nf * 8 + 2 * lt] = w0;
            *(float2*)&Ps[(qrow + lr + 8) * QSTR + nf * 8 + 2 * lt] = w1;
        }
        rs0 += __shfl_xor_sync(0xffffffffu, rs0, 1);
        rs0 += __shfl_xor_sync(0xffffffffu, rs0, 2);
        rs1 += __shfl_xor_sync(0xffffffffu, rs1, 1);
        rs1 += __shfl_xor_sync(0xffffffffu, rs1, 2);
        const float al0 = __expf(m0 - nm0), al1 = __expf(m1 - nm1);
        l0 = l0 * al0 + rs0;
        l1 = l1 * al1 + rs1;
        m0 = nm0; m1 = nm1;
#pragma unroll
        for (int nf = 0; nf < 8; nf++) {
            o[nf][0] *= al0; o[nf][1] *= al0;
            o[nf][2] *= al1; o[nf][3] *= al1;
        }
        __syncwarp();

#pragma unroll
        for (int ks = 0; ks < 8; ks++) {
            const int kk = ks * 8 + lt;
            unsigned pa[4];
            pa[0] = __float_as_uint(Ps[(qrow + lr) * QSTR + kk]);
            pa[1] = __float_as_uint(Ps[(qrow + lr + 8) * QSTR + kk]);
            pa[2] = __float_as_uint(Ps[(qrow + lr) * QSTR + kk + 4]);
            pa[3] = __float_as_uint(Ps[(qrow + lr + 8) * QSTR + kk + 4]);
#pragma unroll
            for (int nf = 0; nf < 8; nf++) {
                unsigned vb2[2];
                vb2[0] = __float_as_uint(Vs[kk * VSTR + nf * 8 + lr]);
                vb2[1] = __float_as_uint(Vs[(kk + 4) * VSTR + nf * 8 + lr]);
                mma_tf32(o[nf], pa, vb2);
            }
        }
    }

    const int b = bh >> 4, h = bh & 15;
    const float inv0 = 1.0f / l0, inv1 = 1.0f / l1;
    const int srow0 = qt * 128 + qrow + lr;
    float* base0 = g_att + ((size_t)b * SS + srow0) * EE + h * DD;
    float* base1 = base0 + (size_t)8 * EE;
#pragma unroll
    for (int nf = 0; nf < 8; nf++) {
        float2 v0 = {o[nf][0] * inv0, o[nf][1] * inv0};
        float2 v1 = {o[nf][2] * inv1, o[nf][3] * inv1};
        *(float2*)(base0 + nf * 8 + 2 * lt) = v0;
        *(float2*)(base1 + nf * 8 + 2 * lt) = v1;
    }
}

// ---------------------------------------------------------------------------
extern "C" void kernel_launch(void* const* d_in, const int* in_sizes, int n_in,
                              void* d_out, int out_size)
{
    const float* x     = (const float*)d_in[0];
    const float* w_qkv = (const float*)d_in[1];
    const float* b_qkv = (const float*)d_in[2];
    const float* w_out = (const float*)d_in[3];
    const float* b_out = (const float*)d_in[4];
    float* out = (float*)d_out;

    (void)in_sizes; (void)n_in; (void)out_size;

    cudaFuncSetAttribute(bf16_gemm<0>,
                         cudaFuncAttributeMaxDynamicSharedMemorySize, GEMM_SMEM);
    cudaFuncSetAttribute(bf16_gemm<1>,
                         cudaFuncAttributeMaxDynamicSharedMemorySize, GEMM_SMEM);
    cudaFuncSetAttribute(fa_tf32,
                         cudaFuncAttributeMaxDynamicSharedMemorySize, FA_SMEM);

    // 1) split + fragment-pack x and w_qkv
    prep_a<0><<<BS * 512 / 256, 256>>>(x);
    prep_b<0><<<512 * N_QKV / 256, 256>>>(w_qkv);
    // 2) QKV projection (split-bf16 HMMA)
    {
        dim3 grid(N_QKV / 128, BS / 128);            // (24, 64)
        bf16_gemm<0><<<grid, 256, GEMM_SMEM>>>(b_qkv, nullptr);
    }
    // 3) attention
    {
        dim3 grid(SS / 128, BB * HH);                // (16, 64)
        fa_tf32<<<grid, 256, FA_SMEM>>>();
    }
    // 4) split + fragment-pack att output and w_out
    prep_a<1><<<BS * 512 / 256, 256>>>(nullptr);
    prep_b<1><<<512 * EE / 256, 256>>>(w_out);
    // 5) output projection (split-bf16 HMMA)
    {
        dim3 grid(EE / 128, BS / 128);               // (8, 64)
        bf16_gemm<1><<<grid, 256, GEMM_SMEM>>>(b_out, out);
    }
}